// round 11
// baseline (speedup 1.0000x reference)
#include <cuda_runtime.h>

// MSAColumnGlobalAttention: B=1, s=1024, i=512, c=8, h=8
// Kernel A (per-column CTA, 256 thr x 4 rows, occ 4 => single wave):
//   raw-normalized xn (gamma folded into qk), xbar -> qk -> exp-sum -> rcp.
//   Writes only g_qk (128KB) + g_rcp (16KB). No 16MB e store.
// Kernel B (streaming, 1 row/thr, 256x4): LN from m, e = exp(x . qk[i])
//   recomputed from the hot qk table, then gate/sigmoid/Wo via f32x2.

#define LN_EPS 1e-5f
#define I_DIM 512
#define S_DIM 1024
#define A_THREADS 256
#define A_NWARP (A_THREADS / 32)
#define B_THREADS 256

struct WeightsB {
    float Wv2[64];
    float Wg2[512];   // pairs over h, PRE-SCALED by 0.5
    float WoP[512];   // pairs over h / co
    float Bo[8];
    float Gamma[8];
    float Beta[8];
};

__device__   WeightsB g_stage;
__constant__ WeightsB cw;
__device__   float g_qk[I_DIM * 64];   // per-column qk, h-paired float4 layout
__device__   float g_rcp[I_DIM * 8];   // 0.5 / (exp(cb) * sum_t exp(dot))

// ---- f32x2 helpers ----
__device__ __forceinline__ float2 fma2(float2 a, float2 b, float2 c) {
    unsigned long long ra = *reinterpret_cast<unsigned long long*>(&a);
    unsigned long long rb = *reinterpret_cast<unsigned long long*>(&b);
    unsigned long long rc = *reinterpret_cast<unsigned long long*>(&c);
    unsigned long long rd;
    asm("fma.rn.f32x2 %0, %1, %2, %3;" : "=l"(rd) : "l"(ra), "l"(rb), "l"(rc));
    return *reinterpret_cast<float2*>(&rd);
}
__device__ __forceinline__ float2 mul2(float2 a, float2 b) {
    unsigned long long ra = *reinterpret_cast<unsigned long long*>(&a);
    unsigned long long rb = *reinterpret_cast<unsigned long long*>(&b);
    unsigned long long rd;
    asm("mul.rn.f32x2 %0, %1, %2;" : "=l"(rd) : "l"(ra), "l"(rb));
    return *reinterpret_cast<float2*>(&rd);
}
__device__ __forceinline__ float2 dup(float x) { return make_float2(x, x); }
__device__ __forceinline__ float2 lo2(float4 w) { return make_float2(w.x, w.y); }
__device__ __forceinline__ float2 hi2(float4 w) { return make_float2(w.z, w.w); }

__device__ __forceinline__ float tanh_apx(float x) {
    float y; asm("tanh.approx.f32 %0, %1;" : "=f"(y) : "f"(x)); return y;
}

#define PAIRDOT8(acc, xd, w0, w1, w2, w3)            \
    acc = mul2(xd[0], lo2(w0));                      \
    acc = fma2(xd[1], hi2(w0), acc);                 \
    acc = fma2(xd[2], lo2(w1), acc);                 \
    acc = fma2(xd[3], hi2(w1), acc);                 \
    acc = fma2(xd[4], lo2(w2), acc);                 \
    acc = fma2(xd[5], hi2(w2), acc);                 \
    acc = fma2(xd[6], lo2(w3), acc);                 \
    acc = fma2(xd[7], hi2(w3), acc);

// Transpose-reduce: lane l ends with warp total of channel (l & 7). 9 SHFLs.
__device__ __forceinline__ float wreduce8(const float v[8], int lane) {
    float a[4];
#pragma unroll
    for (int p = 0; p < 4; p++) {
        const float lo = v[2 * p], hi = v[2 * p + 1];
        const float send = (lane & 1) ? lo : hi;
        const float recv = __shfl_xor_sync(0xffffffffu, send, 1);
        a[p] = ((lane & 1) ? hi : lo) + recv;
    }
    float b[2];
#pragma unroll
    for (int p = 0; p < 2; p++) {
        const float lo = a[2 * p], hi = a[2 * p + 1];
        const float send = (lane & 2) ? lo : hi;
        const float recv = __shfl_xor_sync(0xffffffffu, send, 2);
        b[p] = ((lane & 2) ? hi : lo) + recv;
    }
    {
        const float lo = b[0], hi = b[1];
        const float send = (lane & 4) ? lo : hi;
        const float recv = __shfl_xor_sync(0xffffffffu, send, 4);
        float r = ((lane & 4) ? hi : lo) + recv;
        r += __shfl_xor_sync(0xffffffffu, r, 8);
        r += __shfl_xor_sync(0xffffffffu, r, 16);
        return r;
    }
}

// ============================ Kernel A ============================
__global__ __launch_bounds__(A_THREADS, 4)
void msa_attn_weights_kernel(const float* __restrict__ m,
                             const float* __restrict__ gamma,
                             const float* __restrict__ beta,
                             const float* __restrict__ wq,
                             const float* __restrict__ wk,
                             const float* __restrict__ wv,
                             const float* __restrict__ wg,
                             const float* __restrict__ wo,
                             const float* __restrict__ bo)
{
    const int i    = blockIdx.x;
    const int tid  = threadIdx.x;
    const int lane = tid & 31;
    const int warp = tid >> 5;

    __shared__ float sWq[512];
    __shared__ float sWk[64];
    __shared__ float sRed[A_NWARP][8];
    __shared__ float sXbar[8];
    __shared__ float sQKg[64];   // qk * gamma[j]  (for xn-dots)
    __shared__ float sQKp[64];   // plain qk       (for cb epilogue)

    sWq[tid]       = wq[tid];
    sWq[tid + 256] = wq[tid + 256];
    if (tid < 64) sWk[tid] = wk[tid];

    // CTA 0 repacks streaming weights (overlapped with other CTAs' LN)
    if (i == 0) {
#pragma unroll
        for (int rr = 0; rr < 2; rr++) {
            const int t = tid + rr * 256;
            const int row = t >> 3, j = t & 7;
            const int h = row >> 3, c = row & 7;
            g_stage.Wg2[((h >> 1) * 8 + c) * 16 + (j >> 1) * 4 + (j & 1) * 2 + (h & 1)] = 0.5f * wg[t];
            const int co = t >> 6, idx = t & 63;
            const int hh = idx >> 3, cc = idx & 7;
            g_stage.WoP[(((hh >> 1) * 8 + cc) * 4 + (co >> 1)) * 4 + (co & 1) * 2 + (hh & 1)] = wo[t];
        }
        if (tid < 64) {
            const int c2 = tid >> 3, j2 = tid & 7;
            g_stage.Wv2[(c2 >> 1) * 16 + (j2 >> 1) * 4 + (j2 & 1) * 2 + (c2 & 1)] = wv[tid];
        }
        if (tid < 8) {
            g_stage.Bo[tid]    = bo[tid];
            g_stage.Gamma[tid] = gamma[tid];
            g_stage.Beta[tid]  = beta[tid];
        }
    }

    // ---- phase 1: raw-normalized xn, 4 rows, accumulate column sum ----
    float xn[4][8];
    float acc[8];
#pragma unroll
    for (int c = 0; c < 8; c++) acc[c] = 0.f;

#pragma unroll
    for (int r = 0; r < 4; r++) {
        const size_t gid = (size_t)(r * A_THREADS + tid) * I_DIM + i;
        const float4* p = reinterpret_cast<const float4*>(m + gid * 8);
        float4 a0 = p[0];
        float4 a1 = p[1];
        float xr[8] = {a0.x, a0.y, a0.z, a0.w, a1.x, a1.y, a1.z, a1.w};
        float mean = 0.f;
#pragma unroll
        for (int c = 0; c < 8; c++) mean += xr[c];
        mean *= 0.125f;
        float var = 0.f;
#pragma unroll
        for (int c = 0; c < 8; c++) { float d = xr[c] - mean; var = fmaf(d, d, var); }
        var *= 0.125f;
        const float rstd = rsqrtf(var + LN_EPS);
#pragma unroll
        for (int c = 0; c < 8; c++) {
            xn[r][c] = (xr[c] - mean) * rstd;
            acc[c] += xn[r][c];
        }
    }

    {
        const float r = wreduce8(acc, lane);
        if (lane < 8) sRed[warp][lane] = r;
    }
    __syncthreads();
    if (tid < 8) {
        float s = sRed[0][tid];
#pragma unroll
        for (int w = 1; w < A_NWARP; w++) s += sRed[w][tid];
        // xbar = gamma * sum(xn) + 1024 * beta
        sXbar[tid] = fmaf(__ldg(gamma + tid), s, 1024.f * __ldg(beta + tid));
    }
    __syncthreads();

    // qk[h][j] = sum_c (xbar . Wq[h*8+c]) * Wk[c][j], scaled; store paired to g_qk
    if (tid < 64) {
        const int h = tid >> 3, j = tid & 7;
        float qk = 0.f;
#pragma unroll
        for (int c = 0; c < 8; c++) {
            float q = 0.f;
#pragma unroll
            for (int d = 0; d < 8; d++)
                q = fmaf(sXbar[d], sWq[(h * 8 + c) * 8 + d], q);
            qk = fmaf(q, sWk[c * 8 + j], qk);
        }
        const float qscale = (1.f / 1024.f) * 0.35355339059327373f;
        qk *= qscale;
        sQKp[h * 8 + j] = qk;
        sQKg[h * 8 + j] = qk * __ldg(gamma + j);
        g_qk[i * 64 + (h >> 1) * 16 + (j >> 1) * 4 + (j & 1) * 2 + (h & 1)] = qk;
    }
    __syncthreads();

    // ---- logits on xn (gamma folded into sQKg; beta handled via cb at end) ----
    float hred[8];
#pragma unroll
    for (int h = 0; h < 8; h++) hred[h] = 0.f;

#pragma unroll
    for (int r = 0; r < 4; r++) {
#pragma unroll
        for (int h = 0; h < 8; h++) {
            const float4 qa = *reinterpret_cast<const float4*>(&sQKg[h * 8]);
            const float4 qb = *reinterpret_cast<const float4*>(&sQKg[h * 8 + 4]);
            float a = xn[r][0] * qa.x, b = xn[r][1] * qa.y;
            a = fmaf(xn[r][2], qa.z, a);  b = fmaf(xn[r][3], qa.w, b);
            a = fmaf(xn[r][4], qb.x, a);  b = fmaf(xn[r][5], qb.y, b);
            a = fmaf(xn[r][6], qb.z, a);  b = fmaf(xn[r][7], qb.w, b);
            hred[h] += __expf(a + b);
        }
    }

    {
        const float r = wreduce8(hred, lane);
        if (lane < 8) sRed[warp][lane] = r;
    }
    __syncthreads();
    if (tid < 8) {
        float s = sRed[0][tid];
#pragma unroll
        for (int w = 1; w < A_NWARP; w++) s += sRed[w][tid];
        // cb[h] = sum_j beta[j] * qk[h][j]; denominator gains exp(cb)
        float cb = 0.f;
#pragma unroll
        for (int j = 0; j < 8; j++) cb = fmaf(__ldg(beta + j), sQKp[tid * 8 + j], cb);
        g_rcp[i * 8 + tid] = __fdividef(0.5f, __expf(cb) * s);
    }
}

// ============================ Kernel B ============================
__global__ __launch_bounds__(B_THREADS, 4)
void msa_stream_kernel(const float* __restrict__ m,
                       float* __restrict__ out)
{
    const size_t gid = (size_t)blockIdx.x * B_THREADS + threadIdx.x;  // = s*512 + i
    const int i = (int)(gid & (I_DIM - 1));

    // LN (full x with gamma/beta)
    float2 xd[8];
    {
        const float4* p = reinterpret_cast<const float4*>(m + gid * 8);
        float4 a0 = p[0];
        float4 a1 = p[1];
        float xr[8] = {a0.x, a0.y, a0.z, a0.w, a1.x, a1.y, a1.z, a1.w};
        float mean = 0.f;
#pragma unroll
        for (int c = 0; c < 8; c++) mean += xr[c];
        mean *= 0.125f;
        float var = 0.f;
#pragma unroll
        for (int c = 0; c < 8; c++) { float d = xr[c] - mean; var = fmaf(d, d, var); }
        var *= 0.125f;
        const float rstd = rsqrtf(var + LN_EPS);
#pragma unroll
        for (int c = 0; c < 8; c++)
            xd[c] = dup(fmaf((xr[c] - mean) * rstd, cw.Gamma[c], cw.Beta[c]));
    }

    // e = exp(x . qk[h]) recomputed from the hot per-column table, * rcp
    float2 whp[4];
    {
        const float4* pq = reinterpret_cast<const float4*>(&g_qk[i * 64]);
        const float4* pr = reinterpret_cast<const float4*>(&g_rcp[i * 8]);
        const float4 rA = __ldg(pr), rB = __ldg(pr + 1);
        const float2 rp[4] = {lo2(rA), hi2(rA), lo2(rB), hi2(rB)};
#pragma unroll
        for (int hp = 0; hp < 4; hp++) {
            const float4 q0 = pq[hp * 4], q1 = pq[hp * 4 + 1], q2 = pq[hp * 4 + 2], q3 = pq[hp * 4 + 3];
            float2 l2;
            PAIRDOT8(l2, xd, q0, q1, q2, q3);
            const float2 e2 = make_float2(__expf(l2.x), __expf(l2.y));
            whp[hp] = mul2(e2, rp[hp]);
        }
    }

    float2 v2[4];
#pragma unroll
    for (int cp = 0; cp < 4; cp++) {
        const float4* vp = reinterpret_cast<const float4*>(&cw.Wv2[cp * 16]);
        const float4 w0 = vp[0], w1 = vp[1], w2 = vp[2], w3 = vp[3];
        float2 a;
        PAIRDOT8(a, xd, w0, w1, w2, w3);
        v2[cp] = a;
    }

    float2 o2h[8];
#pragma unroll
    for (int co = 0; co < 8; co++) o2h[co] = make_float2(0.f, 0.f);

#pragma unroll
    for (int hp = 0; hp < 4; hp++) {
        const float2 wh = whp[hp];
#pragma unroll
        for (int c = 0; c < 8; c++) {
            const float4* gp = reinterpret_cast<const float4*>(&cw.Wg2[(hp * 8 + c) * 16]);
            const float4 ga = gp[0], gb = gp[1], gc = gp[2], gd = gp[3];
            float2 g2;
            PAIRDOT8(g2, xd, ga, gb, gc, gd);

            float2 t2 = make_float2(tanh_apx(g2.x), tanh_apx(g2.y));
            const float vc = (c & 1) ? v2[c >> 1].y : v2[c >> 1].x;
            const float2 hv = mul2(wh, dup(vc));
            const float2 coef = fma2(t2, hv, hv);

            const float4* op = reinterpret_cast<const float4*>(&cw.WoP[(hp * 8 + c) * 16]);
            const float4 u0 = op[0], u1 = op[1], u2 = op[2], u3 = op[3];
            o2h[0] = fma2(lo2(u0), coef, o2h[0]);
            o2h[1] = fma2(hi2(u0), coef, o2h[1]);
            o2h[2] = fma2(lo2(u1), coef, o2h[2]);
            o2h[3] = fma2(hi2(u1), coef, o2h[3]);
            o2h[4] = fma2(lo2(u2), coef, o2h[4]);
            o2h[5] = fma2(hi2(u2), coef, o2h[5]);
            o2h[6] = fma2(lo2(u3), coef, o2h[6]);
            o2h[7] = fma2(hi2(u3), coef, o2h[7]);
        }
    }

    float o[8];
#pragma unroll
    for (int co = 0; co < 8; co++) o[co] = (o2h[co].x + o2h[co].y) + cw.Bo[co];

    float4* po = reinterpret_cast<float4*>(out + gid * 8);
    po[0] = make_float4(o[0], o[1], o[2], o[3]);
    po[1] = make_float4(o[4], o[5], o[6], o[7]);
}

extern "C" void kernel_launch(void* const* d_in, const int* in_sizes, int n_in,
                              void* d_out, int out_size) {
    (void)in_sizes; (void)n_in; (void)out_size;
    const float* m  = (const float*)d_in[0];
    float* out      = (float*)d_out;

    msa_attn_weights_kernel<<<I_DIM, A_THREADS>>>(
        m,
        (const float*)d_in[1], (const float*)d_in[2], (const float*)d_in[3],
        (const float*)d_in[4], (const float*)d_in[5], (const float*)d_in[6],
        (const float*)d_in[7], (const float*)d_in[8]);

    void* pstage = nullptr;
    cudaGetSymbolAddress(&pstage, g_stage);
    cudaMemcpyToSymbolAsync(cw, pstage, sizeof(WeightsB), 0, cudaMemcpyDeviceToDevice, 0);

    msa_stream_kernel<<<(S_DIM * I_DIM) / B_THREADS, B_THREADS>>>(m, out);
}

// round 12
// speedup vs baseline: 1.2355x; 1.2355x over previous
#include <cuda_runtime.h>

// MSAColumnGlobalAttention: B=1, s=1024, i=512, c=8, h=8
// Kernel A (per-column CTA, 256 thr x 4 rows, occ 4 => SINGLE WAVE):
//   raw-normalized xn (gamma folded into qk, beta folded into rcp via exp(cb)),
//   xbar -> qk -> e' = exp(xn.(gamma*qk)) stored coalesced -> rcp.
// Kernel B: identical to the proven R10 kernel (25.4us): LN from m, e loaded
//   coalesced from g_w, gate/sigmoid/Wo via f32x2 + constant weights.

#define LN_EPS 1e-5f
#define I_DIM 512
#define S_DIM 1024
#define A_THREADS 256
#define A_NWARP (A_THREADS / 32)
#define B_THREADS 256

struct WeightsB {
    float Wv2[64];
    float Wg2[512];   // pairs over h, PRE-SCALED by 0.5
    float WoP[512];   // pairs over h / co
    float Bo[8];
    float Gamma[8];
    float Beta[8];
};

__device__   WeightsB g_stage;
__constant__ WeightsB cw;
__device__   float g_w[S_DIM * I_DIM * 8];    // e' = exp(xn . (gamma*qk))
__device__   float g_rcp[I_DIM * 8];          // 0.5 / (exp(cb) * sum e')

// ---- f32x2 helpers ----
__device__ __forceinline__ float2 fma2(float2 a, float2 b, float2 c) {
    unsigned long long ra = *reinterpret_cast<unsigned long long*>(&a);
    unsigned long long rb = *reinterpret_cast<unsigned long long*>(&b);
    unsigned long long rc = *reinterpret_cast<unsigned long long*>(&c);
    unsigned long long rd;
    asm("fma.rn.f32x2 %0, %1, %2, %3;" : "=l"(rd) : "l"(ra), "l"(rb), "l"(rc));
    return *reinterpret_cast<float2*>(&rd);
}
__device__ __forceinline__ float2 mul2(float2 a, float2 b) {
    unsigned long long ra = *reinterpret_cast<unsigned long long*>(&a);
    unsigned long long rb = *reinterpret_cast<unsigned long long*>(&b);
    unsigned long long rd;
    asm("mul.rn.f32x2 %0, %1, %2;" : "=l"(rd) : "l"(ra), "l"(rb));
    return *reinterpret_cast<float2*>(&rd);
}
__device__ __forceinline__ float2 dup(float x) { return make_float2(x, x); }
__device__ __forceinline__ float2 lo2(float4 w) { return make_float2(w.x, w.y); }
__device__ __forceinline__ float2 hi2(float4 w) { return make_float2(w.z, w.w); }

__device__ __forceinline__ float tanh_apx(float x) {
    float y; asm("tanh.approx.f32 %0, %1;" : "=f"(y) : "f"(x)); return y;
}

#define PAIRDOT8(acc, xd, w0, w1, w2, w3)            \
    acc = mul2(xd[0], lo2(w0));                      \
    acc = fma2(xd[1], hi2(w0), acc);                 \
    acc = fma2(xd[2], lo2(w1), acc);                 \
    acc = fma2(xd[3], hi2(w1), acc);                 \
    acc = fma2(xd[4], lo2(w2), acc);                 \
    acc = fma2(xd[5], hi2(w2), acc);                 \
    acc = fma2(xd[6], lo2(w3), acc);                 \
    acc = fma2(xd[7], hi2(w3), acc);

// Transpose-reduce: lane l ends with warp total of channel (l & 7). 9 SHFLs.
__device__ __forceinline__ float wreduce8(const float v[8], int lane) {
    float a[4];
#pragma unroll
    for (int p = 0; p < 4; p++) {
        const float lo = v[2 * p], hi = v[2 * p + 1];
        const float send = (lane & 1) ? lo : hi;
        const float recv = __shfl_xor_sync(0xffffffffu, send, 1);
        a[p] = ((lane & 1) ? hi : lo) + recv;
    }
    float b[2];
#pragma unroll
    for (int p = 0; p < 2; p++) {
        const float lo = a[2 * p], hi = a[2 * p + 1];
        const float send = (lane & 2) ? lo : hi;
        const float recv = __shfl_xor_sync(0xffffffffu, send, 2);
        b[p] = ((lane & 2) ? hi : lo) + recv;
    }
    {
        const float lo = b[0], hi = b[1];
        const float send = (lane & 4) ? lo : hi;
        const float recv = __shfl_xor_sync(0xffffffffu, send, 4);
        float r = ((lane & 4) ? hi : lo) + recv;
        r += __shfl_xor_sync(0xffffffffu, r, 8);
        r += __shfl_xor_sync(0xffffffffu, r, 16);
        return r;
    }
}

// ============================ Kernel A ============================
__global__ __launch_bounds__(A_THREADS, 4)
void msa_attn_weights_kernel(const float* __restrict__ m,
                             const float* __restrict__ gamma,
                             const float* __restrict__ beta,
                             const float* __restrict__ wq,
                             const float* __restrict__ wk,
                             const float* __restrict__ wv,
                             const float* __restrict__ wg,
                             const float* __restrict__ wo,
                             const float* __restrict__ bo)
{
    const int i    = blockIdx.x;
    const int tid  = threadIdx.x;
    const int lane = tid & 31;
    const int warp = tid >> 5;

    __shared__ float sWq[512];
    __shared__ float sWk[64];
    __shared__ float sRed[A_NWARP][8];
    __shared__ float sXbar[8];
    __shared__ float sQKg[64];   // qk * gamma[j]  (for xn-dots)
    __shared__ float sQKp[64];   // plain qk       (for cb epilogue)

    sWq[tid]       = wq[tid];
    sWq[tid + 256] = wq[tid + 256];
    if (tid < 64) sWk[tid] = wk[tid];

    // CTA 0 repacks streaming weights (overlapped with other CTAs' LN)
    if (i == 0) {
#pragma unroll
        for (int rr = 0; rr < 2; rr++) {
            const int t = tid + rr * 256;
            const int row = t >> 3, j = t & 7;
            const int h = row >> 3, c = row & 7;
            g_stage.Wg2[((h >> 1) * 8 + c) * 16 + (j >> 1) * 4 + (j & 1) * 2 + (h & 1)] = 0.5f * wg[t];
            const int co = t >> 6, idx = t & 63;
            const int hh = idx >> 3, cc = idx & 7;
            g_stage.WoP[(((hh >> 1) * 8 + cc) * 4 + (co >> 1)) * 4 + (co & 1) * 2 + (hh & 1)] = wo[t];
        }
        if (tid < 64) {
            const int c2 = tid >> 3, j2 = tid & 7;
            g_stage.Wv2[(c2 >> 1) * 16 + (j2 >> 1) * 4 + (j2 & 1) * 2 + (c2 & 1)] = wv[tid];
        }
        if (tid < 8) {
            g_stage.Bo[tid]    = bo[tid];
            g_stage.Gamma[tid] = gamma[tid];
            g_stage.Beta[tid]  = beta[tid];
        }
    }

    // ---- phase 1: raw-normalized xn, 4 rows, accumulate column sum ----
    float xn[4][8];
    {
        float acc[8];
#pragma unroll
        for (int c = 0; c < 8; c++) acc[c] = 0.f;

#pragma unroll
        for (int r = 0; r < 4; r++) {
            const size_t gid = (size_t)(r * A_THREADS + tid) * I_DIM + i;
            const float4* p = reinterpret_cast<const float4*>(m + gid * 8);
            float4 a0 = p[0];
            float4 a1 = p[1];
            float xr[8] = {a0.x, a0.y, a0.z, a0.w, a1.x, a1.y, a1.z, a1.w};
            float mean = 0.f;
#pragma unroll
            for (int c = 0; c < 8; c++) mean += xr[c];
            mean *= 0.125f;
            float var = 0.f;
#pragma unroll
            for (int c = 0; c < 8; c++) { float d = xr[c] - mean; var = fmaf(d, d, var); }
            var *= 0.125f;
            const float rstd = rsqrtf(var + LN_EPS);
#pragma unroll
            for (int c = 0; c < 8; c++) {
                xn[r][c] = (xr[c] - mean) * rstd;
                acc[c] += xn[r][c];
            }
        }
        const float r = wreduce8(acc, lane);
        if (lane < 8) sRed[warp][lane] = r;
    }
    __syncthreads();
    if (tid < 8) {
        float s = sRed[0][tid];
#pragma unroll
        for (int w = 1; w < A_NWARP; w++) s += sRed[w][tid];
        // xbar = gamma * sum(xn) + 1024 * beta
        sXbar[tid] = fmaf(__ldg(gamma + tid), s, 1024.f * __ldg(beta + tid));
    }
    __syncthreads();

    // qk[h][j] = sum_c (xbar . Wq[h*8+c]) * Wk[c][j], scaled
    if (tid < 64) {
        const int h = tid >> 3, j = tid & 7;
        float qk = 0.f;
#pragma unroll
        for (int c = 0; c < 8; c++) {
            float q = 0.f;
#pragma unroll
            for (int d = 0; d < 8; d++)
                q = fmaf(sXbar[d], sWq[(h * 8 + c) * 8 + d], q);
            qk = fmaf(q, sWk[c * 8 + j], qk);
        }
        const float qscale = (1.f / 1024.f) * 0.35355339059327373f;
        qk *= qscale;
        sQKp[h * 8 + j] = qk;
        sQKg[h * 8 + j] = qk * __ldg(gamma + j);
    }
    __syncthreads();

    // ---- logits on xn (gamma in sQKg); store e' per row; accumulate sums ----
    float hred[8];
#pragma unroll
    for (int h = 0; h < 8; h++) hred[h] = 0.f;

#pragma unroll
    for (int r = 0; r < 4; r++) {
        float e[8];
#pragma unroll
        for (int h = 0; h < 8; h++) {
            const float4 qa = *reinterpret_cast<const float4*>(&sQKg[h * 8]);
            const float4 qb = *reinterpret_cast<const float4*>(&sQKg[h * 8 + 4]);
            float a = xn[r][0] * qa.x, b = xn[r][1] * qa.y;
            a = fmaf(xn[r][2], qa.z, a);  b = fmaf(xn[r][3], qa.w, b);
            a = fmaf(xn[r][4], qb.x, a);  b = fmaf(xn[r][5], qb.y, b);
            a = fmaf(xn[r][6], qb.z, a);  b = fmaf(xn[r][7], qb.w, b);
            e[h] = __expf(a + b);
            hred[h] += e[h];
        }
        const size_t gid = (size_t)(r * A_THREADS + tid) * I_DIM + i;
        float4* pw = reinterpret_cast<float4*>(&g_w[gid * 8]);
        pw[0] = make_float4(e[0], e[1], e[2], e[3]);
        pw[1] = make_float4(e[4], e[5], e[6], e[7]);
    }

    {
        const float r = wreduce8(hred, lane);
        if (lane < 8) sRed[warp][lane] = r;
    }
    __syncthreads();
    if (tid < 8) {
        float s = sRed[0][tid];
#pragma unroll
        for (int w = 1; w < A_NWARP; w++) s += sRed[w][tid];
        // cb[h] = beta . qk[h]; e_full/sum e_full == e'/(exp(cb) cancels) — exp(cb)
        // only matters because e' lacks the beta term: fold into denominator.
        float cb = 0.f;
#pragma unroll
        for (int j = 0; j < 8; j++) cb = fmaf(__ldg(beta + j), sQKp[tid * 8 + j], cb);
        (void)cb;  // e' and sum e' are consistent; no correction needed
        g_rcp[i * 8 + tid] = __fdividef(0.5f, s);
    }
}

// ============================ Kernel B (R10, unchanged) ============================
__global__ __launch_bounds__(B_THREADS, 4)
void msa_stream_kernel(const float* __restrict__ m,
                       float* __restrict__ out)
{
    const size_t gid = (size_t)blockIdx.x * B_THREADS + threadIdx.x;  // = s*512 + i
    const int i = (int)(gid & (I_DIM - 1));

    // LN (full x with gamma/beta)
    float2 xd[8];
    {
        const float4* p = reinterpret_cast<const float4*>(m + gid * 8);
        float4 a0 = p[0];
        float4 a1 = p[1];
        float xr[8] = {a0.x, a0.y, a0.z, a0.w, a1.x, a1.y, a1.z, a1.w};
        float mean = 0.f;
#pragma unroll
        for (int c = 0; c < 8; c++) mean += xr[c];
        mean *= 0.125f;
        float var = 0.f;
#pragma unroll
        for (int c = 0; c < 8; c++) { float d = xr[c] - mean; var = fmaf(d, d, var); }
        var *= 0.125f;
        const float rstd = rsqrtf(var + LN_EPS);
#pragma unroll
        for (int c = 0; c < 8; c++)
            xd[c] = dup(fmaf((xr[c] - mean) * rstd, cw.Gamma[c], cw.Beta[c]));
    }

    float2 whp[4];
    {
        const float4* pw = reinterpret_cast<const float4*>(&g_w[gid * 8]);
        const float4 wA = pw[0], wB = pw[1];
        const float4* pr = reinterpret_cast<const float4*>(&g_rcp[i * 8]);
        const float4 rA = __ldg(pr), rB = __ldg(pr + 1);
        whp[0] = mul2(lo2(wA), lo2(rA)); whp[1] = mul2(hi2(wA), hi2(rA));
        whp[2] = mul2(lo2(wB), lo2(rB)); whp[3] = mul2(hi2(wB), hi2(rB));
    }

    float2 v2[4];
#pragma unroll
    for (int cp = 0; cp < 4; cp++) {
        const float4* vp = reinterpret_cast<const float4*>(&cw.Wv2[cp * 16]);
        const float4 w0 = vp[0], w1 = vp[1], w2 = vp[2], w3 = vp[3];
        float2 a;
        PAIRDOT8(a, xd, w0, w1, w2, w3);
        v2[cp] = a;
    }

    float2 o2h[8];
#pragma unroll
    for (int co = 0; co < 8; co++) o2h[co] = make_float2(0.f, 0.f);

#pragma unroll
    for (int hp = 0; hp < 4; hp++) {
        const float2 wh = whp[hp];
#pragma unroll
        for (int c = 0; c < 8; c++) {
            const float4* gp = reinterpret_cast<const float4*>(&cw.Wg2[(hp * 8 + c) * 16]);
            const float4 ga = gp[0], gb = gp[1], gc = gp[2], gd = gp[3];
            float2 g2;
            PAIRDOT8(g2, xd, ga, gb, gc, gd);

            float2 t2 = make_float2(tanh_apx(g2.x), tanh_apx(g2.y));
            const float vc = (c & 1) ? v2[c >> 1].y : v2[c >> 1].x;
            const float2 hv = mul2(wh, dup(vc));
            const float2 coef = fma2(t2, hv, hv);

            const float4* op = reinterpret_cast<const float4*>(&cw.WoP[(hp * 8 + c) * 16]);
            const float4 u0 = op[0], u1 = op[1], u2 = op[2], u3 = op[3];
            o2h[0] = fma2(lo2(u0), coef, o2h[0]);
            o2h[1] = fma2(hi2(u0), coef, o2h[1]);
            o2h[2] = fma2(lo2(u1), coef, o2h[2]);
            o2h[3] = fma2(hi2(u1), coef, o2h[3]);
            o2h[4] = fma2(lo2(u2), coef, o2h[4]);
            o2h[5] = fma2(hi2(u2), coef, o2h[5]);
            o2h[6] = fma2(lo2(u3), coef, o2h[6]);
            o2h[7] = fma2(hi2(u3), coef, o2h[7]);
        }
    }

    float o[8];
#pragma unroll
    for (int co = 0; co < 8; co++) o[co] = (o2h[co].x + o2h[co].y) + cw.Bo[co];

    float4* po = reinterpret_cast<float4*>(out + gid * 8);
    po[0] = make_float4(o[0], o[1], o[2], o[3]);
    po[1] = make_float4(o[4], o[5], o[6], o[7]);
}

extern "C" void kernel_launch(void* const* d_in, const int* in_sizes, int n_in,
                              void* d_out, int out_size) {
    (void)in_sizes; (void)n_in; (void)out_size;
    const float* m  = (const float*)d_in[0];
    float* out      = (float*)d_out;

    msa_attn_weights_kernel<<<I_DIM, A_THREADS>>>(
        m,
        (const float*)d_in[1], (const float*)d_in[2], (const float*)d_in[3],
        (const float*)d_in[4], (const float*)d_in[5], (const float*)d_in[6],
        (const float*)d_in[7], (const float*)d_in[8]);

    void* pstage = nullptr;
    cudaGetSymbolAddress(&pstage, g_stage);
    cudaMemcpyToSymbolAsync(cw, pstage, sizeof(WeightsB), 0, cudaMemcpyDeviceToDevice, 0);

    msa_stream_kernel<<<(S_DIM * I_DIM) / B_THREADS, B_THREADS>>>(m, out);
}

// round 13
// speedup vs baseline: 1.3579x; 1.0991x over previous
#include <cuda_runtime.h>

// MSAColumnGlobalAttention: B=1, s=1024, i=512, c=8, h=8
// R10 structure (proven 41.7us) + gamma-fold in A only:
// Kernel A (per-column CTA, 512 thr x 2 rows, occ 2): raw-normalized xn
//   (no per-row gamma/beta apply); xbar = gamma*sum(xn)+1024*beta; qk;
//   e' = exp(xn.(gamma*qk)) stored coalesced; rcp = 0.5/sum e'
//   (beta factor exp(beta.qk[h]) cancels in e/sum-e).
// Kernel B: byte-identical to R10 (25us control).

#define LN_EPS 1e-5f
#define I_DIM 512
#define S_DIM 1024
#define A_THREADS 512
#define NWARP (A_THREADS / 32)
#define B_THREADS 256

struct WeightsB {
    float Wv2[64];
    float Wg2[512];   // pairs over h, PRE-SCALED by 0.5
    float WoP[512];   // pairs over h / co
    float Bo[8];
    float Gamma[8];
    float Beta[8];
};

__device__   WeightsB g_stage;
__constant__ WeightsB cw;
__device__   float g_w[S_DIM * I_DIM * 8];    // e' = exp(xn . (gamma*qk))
__device__   float g_rcp[I_DIM * 8];          // 0.5 / sum_t e'

// ---- f32x2 helpers ----
__device__ __forceinline__ float2 fma2(float2 a, float2 b, float2 c) {
    unsigned long long ra = *reinterpret_cast<unsigned long long*>(&a);
    unsigned long long rb = *reinterpret_cast<unsigned long long*>(&b);
    unsigned long long rc = *reinterpret_cast<unsigned long long*>(&c);
    unsigned long long rd;
    asm("fma.rn.f32x2 %0, %1, %2, %3;" : "=l"(rd) : "l"(ra), "l"(rb), "l"(rc));
    return *reinterpret_cast<float2*>(&rd);
}
__device__ __forceinline__ float2 mul2(float2 a, float2 b) {
    unsigned long long ra = *reinterpret_cast<unsigned long long*>(&a);
    unsigned long long rb = *reinterpret_cast<unsigned long long*>(&b);
    unsigned long long rd;
    asm("mul.rn.f32x2 %0, %1, %2;" : "=l"(rd) : "l"(ra), "l"(rb));
    return *reinterpret_cast<float2*>(&rd);
}
__device__ __forceinline__ float2 dup(float x) { return make_float2(x, x); }
__device__ __forceinline__ float2 lo2(float4 w) { return make_float2(w.x, w.y); }
__device__ __forceinline__ float2 hi2(float4 w) { return make_float2(w.z, w.w); }

__device__ __forceinline__ float tanh_apx(float x) {
    float y; asm("tanh.approx.f32 %0, %1;" : "=f"(y) : "f"(x)); return y;
}

#define PAIRDOT8(acc, xd, w0, w1, w2, w3)            \
    acc = mul2(xd[0], lo2(w0));                      \
    acc = fma2(xd[1], hi2(w0), acc);                 \
    acc = fma2(xd[2], lo2(w1), acc);                 \
    acc = fma2(xd[3], hi2(w1), acc);                 \
    acc = fma2(xd[4], lo2(w2), acc);                 \
    acc = fma2(xd[5], hi2(w2), acc);                 \
    acc = fma2(xd[6], lo2(w3), acc);                 \
    acc = fma2(xd[7], hi2(w3), acc);

// Transpose-reduce: lane l ends with warp total of channel (l & 7). 9 SHFLs.
__device__ __forceinline__ float wreduce8(const float v[8], int lane) {
    float a[4];
#pragma unroll
    for (int p = 0; p < 4; p++) {
        const float lo = v[2 * p], hi = v[2 * p + 1];
        const float send = (lane & 1) ? lo : hi;
        const float recv = __shfl_xor_sync(0xffffffffu, send, 1);
        a[p] = ((lane & 1) ? hi : lo) + recv;
    }
    float b[2];
#pragma unroll
    for (int p = 0; p < 2; p++) {
        const float lo = a[2 * p], hi = a[2 * p + 1];
        const float send = (lane & 2) ? lo : hi;
        const float recv = __shfl_xor_sync(0xffffffffu, send, 2);
        b[p] = ((lane & 2) ? hi : lo) + recv;
    }
    {
        const float lo = b[0], hi = b[1];
        const float send = (lane & 4) ? lo : hi;
        const float recv = __shfl_xor_sync(0xffffffffu, send, 4);
        float r = ((lane & 4) ? hi : lo) + recv;
        r += __shfl_xor_sync(0xffffffffu, r, 8);
        r += __shfl_xor_sync(0xffffffffu, r, 16);
        return r;
    }
}

// ============================ Kernel A ============================
__global__ __launch_bounds__(A_THREADS, 2)
void msa_attn_weights_kernel(const float* __restrict__ m,
                             const float* __restrict__ gamma,
                             const float* __restrict__ beta,
                             const float* __restrict__ wq,
                             const float* __restrict__ wk,
                             const float* __restrict__ wv,
                             const float* __restrict__ wg,
                             const float* __restrict__ wo,
                             const float* __restrict__ bo)
{
    const int i    = blockIdx.x;
    const int tid  = threadIdx.x;
    const int lane = tid & 31;
    const int warp = tid >> 5;

    __shared__ float sWq[512];
    __shared__ float sWk[64];
    __shared__ float sRed[NWARP][8];
    __shared__ float sXbar[8];
    __shared__ float sQKg[64];   // qk * gamma[j]

    sWq[tid] = wq[tid];
    if (tid < 64) sWk[tid] = wk[tid];

    // CTA 0 repacks streaming weights (overlapped with other CTAs' LN)
    if (i == 0) {
        const int row = tid >> 3, j = tid & 7;
        const int h = row >> 3, c = row & 7;
        g_stage.Wg2[((h >> 1) * 8 + c) * 16 + (j >> 1) * 4 + (j & 1) * 2 + (h & 1)] = 0.5f * wg[tid];
        const int co = tid >> 6, idx = tid & 63;
        const int hh = idx >> 3, cc = idx & 7;
        g_stage.WoP[(((hh >> 1) * 8 + cc) * 4 + (co >> 1)) * 4 + (co & 1) * 2 + (hh & 1)] = wo[tid];
        if (tid < 64) {
            const int c2 = tid >> 3, j2 = tid & 7;
            g_stage.Wv2[(c2 >> 1) * 16 + (j2 >> 1) * 4 + (j2 & 1) * 2 + (c2 & 1)] = wv[tid];
        }
        if (tid < 8) {
            g_stage.Bo[tid]    = bo[tid];
            g_stage.Gamma[tid] = gamma[tid];
            g_stage.Beta[tid]  = beta[tid];
        }
    }

    // ---- LN both rows: RAW normalized xn (gamma/beta folded downstream) ----
    float xn0[8], xn1[8];
#pragma unroll
    for (int r = 0; r < 2; r++) {
        float* xr_out = r ? xn1 : xn0;
        const size_t gid = (size_t)(r * A_THREADS + tid) * I_DIM + i;
        const float4* p = reinterpret_cast<const float4*>(m + gid * 8);
        float4 a0 = p[0];
        float4 a1 = p[1];
        float xr[8] = {a0.x, a0.y, a0.z, a0.w, a1.x, a1.y, a1.z, a1.w};
        float mean = 0.f;
#pragma unroll
        for (int c = 0; c < 8; c++) mean += xr[c];
        mean *= 0.125f;
        float var = 0.f;
#pragma unroll
        for (int c = 0; c < 8; c++) { float d = xr[c] - mean; var = fmaf(d, d, var); }
        var *= 0.125f;
        const float rstd = rsqrtf(var + LN_EPS);
#pragma unroll
        for (int c = 0; c < 8; c++)
            xr_out[c] = (xr[c] - mean) * rstd;
    }

    {
        float acc[8];
#pragma unroll
        for (int c = 0; c < 8; c++) acc[c] = xn0[c] + xn1[c];
        const float r = wreduce8(acc, lane);
        if (lane < 8) sRed[warp][lane] = r;
    }
    __syncthreads();
    if (tid < 8) {
        float s = sRed[0][tid];
#pragma unroll
        for (int w = 1; w < NWARP; w++) s += sRed[w][tid];
        // xbar = gamma * sum(xn) + 1024 * beta   (exact)
        sXbar[tid] = fmaf(__ldg(gamma + tid), s, 1024.f * __ldg(beta + tid));
    }
    __syncthreads();

    // qk[h][j] = sum_c (xbar . Wq[h*8+c]) * Wk[c][j], scaled; fold gamma for xn-dots
    if (tid < 64) {
        const int h = tid >> 3, j = tid & 7;
        float qk = 0.f;
#pragma unroll
        for (int c = 0; c < 8; c++) {
            float q = 0.f;
#pragma unroll
            for (int d = 0; d < 8; d++)
                q = fmaf(sXbar[d], sWq[(h * 8 + c) * 8 + d], q);
            qk = fmaf(q, sWk[c * 8 + j], qk);
        }
        const float qscale = (1.f / 1024.f) * 0.35355339059327373f;
        sQKg[h * 8 + j] = qk * qscale * __ldg(gamma + j);
    }
    __syncthreads();

    // logits on xn -> e' -> store RAW; accumulate per-h sums.
    // Full logit = xn.(gamma*qk) + beta.qk; the beta term is constant in t for
    // fixed (i,h), so exp of it cancels in e/sum-e -> store e' and 0.5/sum e'.
    float hred[8];
    {
        float e0[8], e1[8];
#pragma unroll
        for (int h = 0; h < 8; h++) {
            const float4 qa = *reinterpret_cast<const float4*>(&sQKg[h * 8]);
            const float4 qb = *reinterpret_cast<const float4*>(&sQKg[h * 8 + 4]);
            float a0 = xn0[0] * qa.x, b0 = xn0[1] * qa.y;
            float a1 = xn1[0] * qa.x, b1 = xn1[1] * qa.y;
            a0 = fmaf(xn0[2], qa.z, a0);  b0 = fmaf(xn0[3], qa.w, b0);
            a1 = fmaf(xn1[2], qa.z, a1);  b1 = fmaf(xn1[3], qa.w, b1);
            a0 = fmaf(xn0[4], qb.x, a0);  b0 = fmaf(xn0[5], qb.y, b0);
            a1 = fmaf(xn1[4], qb.x, a1);  b1 = fmaf(xn1[5], qb.y, b1);
            a0 = fmaf(xn0[6], qb.z, a0);  b0 = fmaf(xn0[7], qb.w, b0);
            a1 = fmaf(xn1[6], qb.z, a1);  b1 = fmaf(xn1[7], qb.w, b1);
            e0[h] = __expf(a0 + b0);
            e1[h] = __expf(a1 + b1);
            hred[h] = e0[h] + e1[h];
        }
        float4* pw0 = reinterpret_cast<float4*>(&g_w[((size_t)tid * I_DIM + i) * 8]);
        pw0[0] = make_float4(e0[0], e0[1], e0[2], e0[3]);
        pw0[1] = make_float4(e0[4], e0[5], e0[6], e0[7]);
        float4* pw1 = reinterpret_cast<float4*>(&g_w[((size_t)(tid + A_THREADS) * I_DIM + i) * 8]);
        pw1[0] = make_float4(e1[0], e1[1], e1[2], e1[3]);
        pw1[1] = make_float4(e1[4], e1[5], e1[6], e1[7]);
    }

    {
        const float r = wreduce8(hred, lane);
        if (lane < 8) sRed[warp][lane] = r;
    }
    __syncthreads();
    if (tid < 8) {
        float s = sRed[0][tid];
#pragma unroll
        for (int w = 1; w < NWARP; w++) s += sRed[w][tid];
        g_rcp[i * 8 + tid] = __fdividef(0.5f, s);
    }
}

// ============================ Kernel B (R10, unchanged) ============================
__global__ __launch_bounds__(B_THREADS, 4)
void msa_stream_kernel(const float* __restrict__ m,
                       float* __restrict__ out)
{
    const size_t gid = (size_t)blockIdx.x * B_THREADS + threadIdx.x;  // = s*512 + i
    const int i = (int)(gid & (I_DIM - 1));

    // LN (full x with gamma/beta)
    float2 xd[8];
    {
        const float4* p = reinterpret_cast<const float4*>(m + gid * 8);
        float4 a0 = p[0];
        float4 a1 = p[1];
        float xr[8] = {a0.x, a0.y, a0.z, a0.w, a1.x, a1.y, a1.z, a1.w};
        float mean = 0.f;
#pragma unroll
        for (int c = 0; c < 8; c++) mean += xr[c];
        mean *= 0.125f;
        float var = 0.f;
#pragma unroll
        for (int c = 0; c < 8; c++) { float d = xr[c] - mean; var = fmaf(d, d, var); }
        var *= 0.125f;
        const float rstd = rsqrtf(var + LN_EPS);
#pragma unroll
        for (int c = 0; c < 8; c++)
            xd[c] = dup(fmaf((xr[c] - mean) * rstd, cw.Gamma[c], cw.Beta[c]));
    }

    float2 whp[4];
    {
        const float4* pw = reinterpret_cast<const float4*>(&g_w[gid * 8]);
        const float4 wA = pw[0], wB = pw[1];
        const float4* pr = reinterpret_cast<const float4*>(&g_rcp[i * 8]);
        const float4 rA = __ldg(pr), rB = __ldg(pr + 1);
        whp[0] = mul2(lo2(wA), lo2(rA)); whp[1] = mul2(hi2(wA), hi2(rA));
        whp[2] = mul2(lo2(wB), lo2(rB)); whp[3] = mul2(hi2(wB), hi2(rB));
    }

    float2 v2[4];
#pragma unroll
    for (int cp = 0; cp < 4; cp++) {
        const float4* vp = reinterpret_cast<const float4*>(&cw.Wv2[cp * 16]);
        const float4 w0 = vp[0], w1 = vp[1], w2 = vp[2], w3 = vp[3];
        float2 a;
        PAIRDOT8(a, xd, w0, w1, w2, w3);
        v2[cp] = a;
    }

    float2 o2h[8];
#pragma unroll
    for (int co = 0; co < 8; co++) o2h[co] = make_float2(0.f, 0.f);

#pragma unroll
    for (int hp = 0; hp < 4; hp++) {
        const float2 wh = whp[hp];
#pragma unroll
        for (int c = 0; c < 8; c++) {
            const float4* gp = reinterpret_cast<const float4*>(&cw.Wg2[(hp * 8 + c) * 16]);
            const float4 ga = gp[0], gb = gp[1], gc = gp[2], gd = gp[3];
            float2 g2;
            PAIRDOT8(g2, xd, ga, gb, gc, gd);

            float2 t2 = make_float2(tanh_apx(g2.x), tanh_apx(g2.y));
            const float vc = (c & 1) ? v2[c >> 1].y : v2[c >> 1].x;
            const float2 hv = mul2(wh, dup(vc));
            const float2 coef = fma2(t2, hv, hv);

            const float4* op = reinterpret_cast<const float4*>(&cw.WoP[(hp * 8 + c) * 16]);
            const float4 u0 = op[0], u1 = op[1], u2 = op[2], u3 = op[3];
            o2h[0] = fma2(lo2(u0), coef, o2h[0]);
            o2h[1] = fma2(hi2(u0), coef, o2h[1]);
            o2h[2] = fma2(lo2(u1), coef, o2h[2]);
            o2h[3] = fma2(hi2(u1), coef, o2h[3]);
            o2h[4] = fma2(lo2(u2), coef, o2h[4]);
            o2h[5] = fma2(hi2(u2), coef, o2h[5]);
            o2h[6] = fma2(lo2(u3), coef, o2h[6]);
            o2h[7] = fma2(hi2(u3), coef, o2h[7]);
        }
    }

    float o[8];
#pragma unroll
    for (int co = 0; co < 8; co++) o[co] = (o2h[co].x + o2h[co].y) + cw.Bo[co];

    float4* po = reinterpret_cast<float4*>(out + gid * 8);
    po[0] = make_float4(o[0], o[1], o[2], o[3]);
    po[1] = make_float4(o[4], o[5], o[6], o[7]);
}

extern "C" void kernel_launch(void* const* d_in, const int* in_sizes, int n_in,
                              void* d_out, int out_size) {
    (void)in_sizes; (void)n_in; (void)out_size;
    const float* m  = (const float*)d_in[0];
    float* out      = (float*)d_out;

    msa_attn_weights_kernel<<<I_DIM, A_THREADS>>>(
        m,
        (const float*)d_in[1], (const float*)d_in[2], (const float*)d_in[3],
        (const float*)d_in[4], (const float*)d_in[5], (const float*)d_in[6],
        (const float*)d_in[7], (const float*)d_in[8]);

    void* pstage = nullptr;
    cudaGetSymbolAddress(&pstage, g_stage);
    cudaMemcpyToSymbolAsync(cw, pstage, sizeof(WeightsB), 0, cudaMemcpyDeviceToDevice, 0);

    msa_stream_kernel<<<(S_DIM * I_DIM) / B_THREADS, B_THREADS>>>(m, out);
}

// round 14
// speedup vs baseline: 1.5150x; 1.1157x over previous
#include <cuda_runtime.h>

// MSAColumnGlobalAttention: B=1, s=1024, i=512, c=8, h=8
// Kernel A (4 columns/CTA, 512 thr, grid 128, COALESCED):
//   lane -> (i_local = t&3, strand = t>>2); warp reads 4 adjacent columns
//   per s-group = full 128B lines (8 wavefronts per LDG vs 32 before).
//   Pass 1: LN sums (xn transient) -> xbar -> qk (gamma-folded, SMEM pad 72).
//   Pass 2: re-read m (L2-hot), recompute LN, e'=exp(xn.(gamma*qk)) stored
//   coalesced, 0.5/sum e' -> g_rcp.
// Kernel B: byte-identical to R10/R13 control (25.2us).

#define LN_EPS 1e-5f
#define I_DIM 512
#define S_DIM 1024
#define A_THREADS 512
#define A_NWARP (A_THREADS / 32)
#define CPG 4                      // columns per CTA
#define NSTRAND (A_THREADS / CPG)  // 128 s-strands
#define ROWS_PT (S_DIM / NSTRAND)  // 8 rows per thread
#define QK_PAD 72                  // conflict-free stride for sQKg
#define B_THREADS 256

struct WeightsB {
    float Wv2[64];
    float Wg2[512];   // pairs over h, PRE-SCALED by 0.5
    float WoP[512];   // pairs over h / co
    float Bo[8];
    float Gamma[8];
    float Beta[8];
};

__device__   WeightsB g_stage;
__constant__ WeightsB cw;
__device__   float g_w[S_DIM * I_DIM * 8];    // e' = exp(xn . (gamma*qk))
__device__   float g_rcp[I_DIM * 8];          // 0.5 / sum_t e'

// ---- f32x2 helpers ----
__device__ __forceinline__ float2 fma2(float2 a, float2 b, float2 c) {
    unsigned long long ra = *reinterpret_cast<unsigned long long*>(&a);
    unsigned long long rb = *reinterpret_cast<unsigned long long*>(&b);
    unsigned long long rc = *reinterpret_cast<unsigned long long*>(&c);
    unsigned long long rd;
    asm("fma.rn.f32x2 %0, %1, %2, %3;" : "=l"(rd) : "l"(ra), "l"(rb), "l"(rc));
    return *reinterpret_cast<float2*>(&rd);
}
__device__ __forceinline__ float2 mul2(float2 a, float2 b) {
    unsigned long long ra = *reinterpret_cast<unsigned long long*>(&a);
    unsigned long long rb = *reinterpret_cast<unsigned long long*>(&b);
    unsigned long long rd;
    asm("mul.rn.f32x2 %0, %1, %2;" : "=l"(rd) : "l"(ra), "l"(rb));
    return *reinterpret_cast<float2*>(&rd);
}
__device__ __forceinline__ float2 dup(float x) { return make_float2(x, x); }
__device__ __forceinline__ float2 lo2(float4 w) { return make_float2(w.x, w.y); }
__device__ __forceinline__ float2 hi2(float4 w) { return make_float2(w.z, w.w); }

__device__ __forceinline__ float tanh_apx(float x) {
    float y; asm("tanh.approx.f32 %0, %1;" : "=f"(y) : "f"(x)); return y;
}

#define PAIRDOT8(acc, xd, w0, w1, w2, w3)            \
    acc = mul2(xd[0], lo2(w0));                      \
    acc = fma2(xd[1], hi2(w0), acc);                 \
    acc = fma2(xd[2], lo2(w1), acc);                 \
    acc = fma2(xd[3], hi2(w1), acc);                 \
    acc = fma2(xd[4], lo2(w2), acc);                 \
    acc = fma2(xd[5], hi2(w2), acc);                 \
    acc = fma2(xd[6], lo2(w3), acc);                 \
    acc = fma2(xd[7], hi2(w3), acc);

// ============================ Kernel A ============================
__global__ __launch_bounds__(A_THREADS)
void msa_attn_weights_kernel(const float* __restrict__ m,
                             const float* __restrict__ gamma,
                             const float* __restrict__ beta,
                             const float* __restrict__ wq,
                             const float* __restrict__ wk,
                             const float* __restrict__ wv,
                             const float* __restrict__ wg,
                             const float* __restrict__ wo,
                             const float* __restrict__ bo)
{
    const int i0     = blockIdx.x * CPG;
    const int tid    = threadIdx.x;
    const int lane   = tid & 31;
    const int il     = tid & (CPG - 1);      // column within group
    const int strand = tid >> 2;             // 0..127
    const int warp   = tid >> 5;
    const int i      = i0 + il;

    __shared__ float sWq[512];
    __shared__ float sWk[64];
    __shared__ float sRed[A_NWARP][CPG][8];
    __shared__ float sXbar[CPG][8];
    __shared__ float sQKg[CPG][QK_PAD];       // qk * gamma, padded stride 72

    sWq[tid] = wq[tid];
    if (tid < 64) sWk[tid] = wk[tid];

    // CTA 0 repacks streaming weights (overlapped with other CTAs' work)
    if (blockIdx.x == 0) {
        const int row = tid >> 3, j = tid & 7;
        const int h = row >> 3, c = row & 7;
        g_stage.Wg2[((h >> 1) * 8 + c) * 16 + (j >> 1) * 4 + (j & 1) * 2 + (h & 1)] = 0.5f * wg[tid];
        const int co = tid >> 6, idx = tid & 63;
        const int hh = idx >> 3, cc = idx & 7;
        g_stage.WoP[(((hh >> 1) * 8 + cc) * 4 + (co >> 1)) * 4 + (co & 1) * 2 + (hh & 1)] = wo[tid];
        if (tid < 64) {
            const int c2 = tid >> 3, j2 = tid & 7;
            g_stage.Wv2[(c2 >> 1) * 16 + (j2 >> 1) * 4 + (j2 & 1) * 2 + (c2 & 1)] = wv[tid];
        }
        if (tid < 8) {
            g_stage.Bo[tid]    = bo[tid];
            g_stage.Gamma[tid] = gamma[tid];
            g_stage.Beta[tid]  = beta[tid];
        }
    }

    // ---- PASS 1: LN sums over this thread's 8 rows (xn transient) ----
    float acc[8];
#pragma unroll
    for (int c = 0; c < 8; c++) acc[c] = 0.f;

#pragma unroll
    for (int r = 0; r < ROWS_PT; r++) {
        const int s = strand + r * NSTRAND;
        const size_t gid = (size_t)s * I_DIM + i;
        const float4* p = reinterpret_cast<const float4*>(m + gid * 8);
        float4 a0 = p[0];
        float4 a1 = p[1];
        float xr[8] = {a0.x, a0.y, a0.z, a0.w, a1.x, a1.y, a1.z, a1.w};
        float mean = 0.f;
#pragma unroll
        for (int c = 0; c < 8; c++) mean += xr[c];
        mean *= 0.125f;
        float var = 0.f;
#pragma unroll
        for (int c = 0; c < 8; c++) { float d = xr[c] - mean; var = fmaf(d, d, var); }
        var *= 0.125f;
        const float rstd = rsqrtf(var + LN_EPS);
#pragma unroll
        for (int c = 0; c < 8; c++)
            acc[c] = fmaf(xr[c] - mean, rstd, acc[c]);
    }

    // reduce over strands sharing il within warp: shfl 4, 8, 16
#pragma unroll
    for (int c = 0; c < 8; c++) {
        acc[c] += __shfl_xor_sync(0xffffffffu, acc[c], 4);
        acc[c] += __shfl_xor_sync(0xffffffffu, acc[c], 8);
        acc[c] += __shfl_xor_sync(0xffffffffu, acc[c], 16);
    }
    if (lane < CPG) {
#pragma unroll
        for (int c = 0; c < 8; c++) sRed[warp][lane][c] = acc[c];
    }
    __syncthreads();
    if (tid < CPG * 8) {
        const int jl = tid >> 3, c = tid & 7;
        float s = sRed[0][jl][c];
#pragma unroll
        for (int w = 1; w < A_NWARP; w++) s += sRed[w][jl][c];
        // xbar = gamma * sum(xn) + 1024 * beta   (exact)
        sXbar[jl][c] = fmaf(__ldg(gamma + c), s, 1024.f * __ldg(beta + c));
    }
    __syncthreads();

    // qk for 4 columns: tid < 256 -> (il2, h, j)
    if (tid < CPG * 64) {
        const int il2 = tid >> 6;
        const int hj  = tid & 63;
        const int h = hj >> 3, j = hj & 7;
        float qk = 0.f;
#pragma unroll
        for (int c = 0; c < 8; c++) {
            float q = 0.f;
#pragma unroll
            for (int d = 0; d < 8; d++)
                q = fmaf(sXbar[il2][d], sWq[(h * 8 + c) * 8 + d], q);
            qk = fmaf(q, sWk[c * 8 + j], qk);
        }
        const float qscale = (1.f / 1024.f) * 0.35355339059327373f;
        sQKg[il2][h * 8 + j] = qk * qscale * __ldg(gamma + j);
    }
    __syncthreads();

    // ---- PASS 2: re-read m (L2-hot), recompute LN, e' -> store, sum ----
    float hred[8];
#pragma unroll
    for (int h = 0; h < 8; h++) hred[h] = 0.f;

#pragma unroll
    for (int r = 0; r < ROWS_PT; r++) {
        const int s = strand + r * NSTRAND;
        const size_t gid = (size_t)s * I_DIM + i;
        const float4* p = reinterpret_cast<const float4*>(m + gid * 8);
        float4 a0 = p[0];
        float4 a1 = p[1];
        float xn[8] = {a0.x, a0.y, a0.z, a0.w, a1.x, a1.y, a1.z, a1.w};
        float mean = 0.f;
#pragma unroll
        for (int c = 0; c < 8; c++) mean += xn[c];
        mean *= 0.125f;
        float var = 0.f;
#pragma unroll
        for (int c = 0; c < 8; c++) { float d = xn[c] - mean; var = fmaf(d, d, var); }
        var *= 0.125f;
        const float rstd = rsqrtf(var + LN_EPS);
#pragma unroll
        for (int c = 0; c < 8; c++)
            xn[c] = (xn[c] - mean) * rstd;

        float e[8];
#pragma unroll
        for (int h = 0; h < 8; h++) {
            const float4 qa = *reinterpret_cast<const float4*>(&sQKg[il][h * 8]);
            const float4 qb = *reinterpret_cast<const float4*>(&sQKg[il][h * 8 + 4]);
            float a = xn[0] * qa.x, b = xn[1] * qa.y;
            a = fmaf(xn[2], qa.z, a);  b = fmaf(xn[3], qa.w, b);
            a = fmaf(xn[4], qb.x, a);  b = fmaf(xn[5], qb.y, b);
            a = fmaf(xn[6], qb.z, a);  b = fmaf(xn[7], qb.w, b);
            e[h] = __expf(a + b);
            hred[h] += e[h];
        }
        float4* pw = reinterpret_cast<float4*>(&g_w[gid * 8]);
        pw[0] = make_float4(e[0], e[1], e[2], e[3]);
        pw[1] = make_float4(e[4], e[5], e[6], e[7]);
    }

#pragma unroll
    for (int h = 0; h < 8; h++) {
        hred[h] += __shfl_xor_sync(0xffffffffu, hred[h], 4);
        hred[h] += __shfl_xor_sync(0xffffffffu, hred[h], 8);
        hred[h] += __shfl_xor_sync(0xffffffffu, hred[h], 16);
    }
    if (lane < CPG) {
#pragma unroll
        for (int h = 0; h < 8; h++) sRed[warp][lane][h] = hred[h];
    }
    __syncthreads();
    if (tid < CPG * 8) {
        const int jl = tid >> 3, h = tid & 7;
        float s = sRed[0][jl][h];
#pragma unroll
        for (int w = 1; w < A_NWARP; w++) s += sRed[w][jl][h];
        g_rcp[(i0 + jl) * 8 + h] = __fdividef(0.5f, s);
    }
}

// ============================ Kernel B (R10, unchanged) ============================
__global__ __launch_bounds__(B_THREADS, 4)
void msa_stream_kernel(const float* __restrict__ m,
                       float* __restrict__ out)
{
    const size_t gid = (size_t)blockIdx.x * B_THREADS + threadIdx.x;  // = s*512 + i
    const int i = (int)(gid & (I_DIM - 1));

    // LN (full x with gamma/beta)
    float2 xd[8];
    {
        const float4* p = reinterpret_cast<const float4*>(m + gid * 8);
        float4 a0 = p[0];
        float4 a1 = p[1];
        float xr[8] = {a0.x, a0.y, a0.z, a0.w, a1.x, a1.y, a1.z, a1.w};
        float mean = 0.f;
#pragma unroll
        for (int c = 0; c < 8; c++) mean += xr[c];
        mean *= 0.125f;
        float var = 0.f;
#pragma unroll
        for (int c = 0; c < 8; c++) { float d = xr[c] - mean; var = fmaf(d, d, var); }
        var *= 0.125f;
        const float rstd = rsqrtf(var + LN_EPS);
#pragma unroll
        for (int c = 0; c < 8; c++)
            xd[c] = dup(fmaf((xr[c] - mean) * rstd, cw.Gamma[c], cw.Beta[c]));
    }

    float2 whp[4];
    {
        const float4* pw = reinterpret_cast<const float4*>(&g_w[gid * 8]);
        const float4 wA = pw[0], wB = pw[1];
        const float4* pr = reinterpret_cast<const float4*>(&g_rcp[i * 8]);
        const float4 rA = __ldg(pr), rB = __ldg(pr + 1);
        whp[0] = mul2(lo2(wA), lo2(rA)); whp[1] = mul2(hi2(wA), hi2(rA));
        whp[2] = mul2(lo2(wB), lo2(rB)); whp[3] = mul2(hi2(wB), hi2(rB));
    }

    float2 v2[4];
#pragma unroll
    for (int cp = 0; cp < 4; cp++) {
        const float4* vp = reinterpret_cast<const float4*>(&cw.Wv2[cp * 16]);
        const float4 w0 = vp[0], w1 = vp[1], w2 = vp[2], w3 = vp[3];
        float2 a;
        PAIRDOT8(a, xd, w0, w1, w2, w3);
        v2[cp] = a;
    }

    float2 o2h[8];
#pragma unroll
    for (int co = 0; co < 8; co++) o2h[co] = make_float2(0.f, 0.f);

#pragma unroll
    for (int hp = 0; hp < 4; hp++) {
        const float2 wh = whp[hp];
#pragma unroll
        for (int c = 0; c < 8; c++) {
            const float4* gp = reinterpret_cast<const float4*>(&cw.Wg2[(hp * 8 + c) * 16]);
            const float4 ga = gp[0], gb = gp[1], gc = gp[2], gd = gp[3];
            float2 g2;
            PAIRDOT8(g2, xd, ga, gb, gc, gd);

            float2 t2 = make_float2(tanh_apx(g2.x), tanh_apx(g2.y));
            const float vc = (c & 1) ? v2[c >> 1].y : v2[c >> 1].x;
            const float2 hv = mul2(wh, dup(vc));
            const float2 coef = fma2(t2, hv, hv);

            const float4* op = reinterpret_cast<const float4*>(&cw.WoP[(hp * 8 + c) * 16]);
            const float4 u0 = op[0], u1 = op[1], u2 = op[2], u3 = op[3];
            o2h[0] = fma2(lo2(u0), coef, o2h[0]);
            o2h[1] = fma2(hi2(u0), coef, o2h[1]);
            o2h[2] = fma2(lo2(u1), coef, o2h[2]);
            o2h[3] = fma2(hi2(u1), coef, o2h[3]);
            o2h[4] = fma2(lo2(u2), coef, o2h[4]);
            o2h[5] = fma2(hi2(u2), coef, o2h[5]);
            o2h[6] = fma2(lo2(u3), coef, o2h[6]);
            o2h[7] = fma2(hi2(u3), coef, o2h[7]);
        }
    }

    float o[8];
#pragma unroll
    for (int co = 0; co < 8; co++) o[co] = (o2h[co].x + o2h[co].y) + cw.Bo[co];

    float4* po = reinterpret_cast<float4*>(out + gid * 8);
    po[0] = make_float4(o[0], o[1], o[2], o[3]);
    po[1] = make_float4(o[4], o[5], o[6], o[7]);
}

extern "C" void kernel_launch(void* const* d_in, const int* in_sizes, int n_in,
                              void* d_out, int out_size) {
    (void)in_sizes; (void)n_in; (void)out_size;
    const float* m  = (const float*)d_in[0];
    float* out      = (float*)d_out;

    msa_attn_weights_kernel<<<I_DIM / CPG, A_THREADS>>>(
        m,
        (const float*)d_in[1], (const float*)d_in[2], (const float*)d_in[3],
        (const float*)d_in[4], (const float*)d_in[5], (const float*)d_in[6],
        (const float*)d_in[7], (const float*)d_in[8]);

    void* pstage = nullptr;
    cudaGetSymbolAddress(&pstage, g_stage);
    cudaMemcpyToSymbolAsync(cw, pstage, sizeof(WeightsB), 0, cudaMemcpyDeviceToDevice, 0);

    msa_stream_kernel<<<(S_DIM * I_DIM) / B_THREADS, B_THREADS>>>(m, out);
}